// round 1
// baseline (speedup 1.0000x reference)
#include <cuda_runtime.h>
#include <math.h>

// Problem constants
#define B_   2
#define C_   4
#define F_   512
#define H_   8
#define W_   1024
#define DH_  64
#define KW   3
#define BC_  (B_*C_)          // 8
#define BCH_ (B_*C_*H_)       // 64
#define PLANE_ (F_*W_)        // 524288 per (b,c)
#define TOT_   (B_*C_*F_*W_)  // 4194304

// Scratch (device globals; no allocations allowed)
__device__ float g_lin[3][TOT_];
__device__ float g_conv[3][TOT_];
__device__ float g_abuf[TOT_];

// ---------------------------------------------------------------------------
// Per-channel GEMM: Y[bc][g][w] = sum_f Wt[c][g][f] * X[bc][f][w]
// Tiles: 64x64 output, K-tile 16, 256 threads, 4x4 register microtile.
// ---------------------------------------------------------------------------
__global__ void __launch_bounds__(256) gemm_lin_kernel(
    const float* __restrict__ Wt, const float* __restrict__ X, float* __restrict__ Y)
{
    const int bc = blockIdx.z;
    const int c  = bc % C_;
    const float* Wc = Wt + (size_t)c * F_ * F_;
    const float* Xb = X  + (size_t)bc * PLANE_;
    float*       Yb = Y  + (size_t)bc * PLANE_;

    __shared__ float As[16][64];   // As[k][m]
    __shared__ float Bs[16][64];   // Bs[k][n]

    const int tid = threadIdx.x;
    const int tn  = tid & 15;      // 0..15
    const int tm  = tid >> 4;      // 0..15
    const int m0  = blockIdx.y * 64;
    const int n0  = blockIdx.x * 64;

    float acc[4][4] = {};

    for (int k0 = 0; k0 < F_; k0 += 16) {
        // A tile: 64 m x 16 k, each thread one float4 along k
        {
            int m  = tid >> 2;           // 0..63
            int kk = (tid & 3) * 4;      // 0,4,8,12
            float4 a = *(const float4*)(Wc + (size_t)(m0 + m) * F_ + k0 + kk);
            As[kk+0][m] = a.x; As[kk+1][m] = a.y; As[kk+2][m] = a.z; As[kk+3][m] = a.w;
        }
        // B tile: 16 k x 64 n, coalesced float4
        {
            int kk = tid >> 4;           // 0..15
            int nn = (tid & 15) * 4;
            *(float4*)&Bs[kk][nn] = *(const float4*)(Xb + (size_t)(k0 + kk) * W_ + n0 + nn);
        }
        __syncthreads();
        #pragma unroll
        for (int kk = 0; kk < 16; kk++) {
            float4 a = *(const float4*)&As[kk][tm*4];
            float4 b = *(const float4*)&Bs[kk][tn*4];
            float ra[4] = {a.x,a.y,a.z,a.w};
            float rb[4] = {b.x,b.y,b.z,b.w};
            #pragma unroll
            for (int i = 0; i < 4; i++)
                #pragma unroll
                for (int j = 0; j < 4; j++)
                    acc[i][j] += ra[i] * rb[j];
        }
        __syncthreads();
    }
    #pragma unroll
    for (int i = 0; i < 4; i++) {
        float4 v = make_float4(acc[i][0], acc[i][1], acc[i][2], acc[i][3]);
        *(float4*)(Yb + (size_t)(m0 + tm*4 + i) * W_ + n0 + tn*4) = v;
    }
}

// ---------------------------------------------------------------------------
// Conv2d(C,C,(1,3),pad=(0,1)) + bias.  y[b,o,f,w] = b[o] + sum_{i,k} w[o,i,k]*x[b,i,f,w+k-1]
// ---------------------------------------------------------------------------
__global__ void __launch_bounds__(256) conv_kernel(
    const float* __restrict__ X, const float* __restrict__ Wc,
    const float* __restrict__ bias, float* __restrict__ Y)
{
    __shared__ float ws[C_*C_*KW];
    __shared__ float bs[C_];
    if (threadIdx.x < C_*C_*KW) ws[threadIdx.x] = Wc[threadIdx.x];
    if (threadIdx.x < C_)       bs[threadIdx.x] = bias[threadIdx.x];
    __syncthreads();

    int idx = blockIdx.x * 256 + threadIdx.x;
    if (idx >= TOT_) return;
    int w = idx & (W_ - 1);
    int f = (idx >> 10) & (F_ - 1);
    int o = (idx >> 19) & (C_ - 1);
    int b = idx >> 21;

    float s = bs[o];
    #pragma unroll
    for (int i = 0; i < C_; i++) {
        const float* xr = X + ((size_t)(b*C_ + i) * F_ + f) * W_ + w;
        #pragma unroll
        for (int k = 0; k < KW; k++) {
            int ww = w + k - 1;
            if (ww >= 0 && ww < W_)
                s += ws[(o*C_ + i)*KW + k] * xr[k - 1];
        }
    }
    Y[idx] = s;
}

// ---------------------------------------------------------------------------
// Interleaved rotary over seq=w, head dim 64 (feature f = h*64 + d), in place.
// ---------------------------------------------------------------------------
__global__ void __launch_bounds__(256) rotary_kernel(float* __restrict__ X)
{
    int pid = blockIdx.x * 256 + threadIdx.x;       // over BCH_*32*W_
    if (pid >= BCH_ * 32 * W_) return;
    int w   = pid & (W_ - 1);
    int j   = (pid >> 10) & 31;                     // pair index 0..31
    int bch = pid >> 15;
    int h   = bch & (H_ - 1);
    int bc  = bch >> 3;

    size_t base = ((size_t)bc * F_ + h * DH_ + 2*j) * W_ + w;
    float x0 = X[base];
    float x1 = X[base + W_];

    float inv = (float)exp(-log(10000.0) * ((double)(2*j) / 64.0));
    float ang = (float)w * inv;
    float sn, cs;
    sincosf(ang, &sn, &cs);

    X[base]       = x0 * cs - x1 * sn;
    X[base + W_]  = x1 * cs + x0 * sn;
}

// ---------------------------------------------------------------------------
// qk[bch][q][k] = (1/sqrt(512)) * sum_d Q[d][q]*K[d][k] + prev + mask
// 64x64 tile per block, K=64 fully in smem.
// ---------------------------------------------------------------------------
__global__ void __launch_bounds__(256) qk_kernel(
    const float* __restrict__ Q, const float* __restrict__ Kb,
    const float* __restrict__ prev, const float* __restrict__ mask,
    float* __restrict__ qk)
{
    const int bch = blockIdx.z;
    const int h   = bch & (H_ - 1);
    const int bc  = bch >> 3;
    const size_t fbase = (size_t)bc * F_ + h * DH_;
    const int q0 = blockIdx.y * 64;
    const int k0 = blockIdx.x * 64;

    __shared__ float Qs[64][64];
    __shared__ float Ks[64][64];

    const int tid = threadIdx.x;
    #pragma unroll
    for (int t = 0; t < 4; t++) {
        int i  = tid + t * 256;       // over 1024 float4 per tile
        int d  = i >> 4;
        int qq = (i & 15) * 4;
        *(float4*)&Qs[d][qq] = *(const float4*)(Q  + (fbase + d) * W_ + q0 + qq);
        *(float4*)&Ks[d][qq] = *(const float4*)(Kb + (fbase + d) * W_ + k0 + qq);
    }
    __syncthreads();

    const int tn = tid & 15, tm = tid >> 4;
    float acc[4][4] = {};
    #pragma unroll
    for (int d = 0; d < 64; d++) {
        float4 a = *(const float4*)&Qs[d][tm*4];
        float4 b = *(const float4*)&Ks[d][tn*4];
        float ra[4] = {a.x,a.y,a.z,a.w};
        float rb[4] = {b.x,b.y,b.z,b.w};
        #pragma unroll
        for (int i = 0; i < 4; i++)
            #pragma unroll
            for (int j = 0; j < 4; j++)
                acc[i][j] += ra[i] * rb[j];
    }

    const float scale = 0.044194173824159216f;   // 1/sqrt(512)
    #pragma unroll
    for (int i = 0; i < 4; i++) {
        int q = q0 + tm*4 + i;
        size_t o = ((size_t)bch * W_ + q) * W_ + k0 + tn*4;
        float4 pv = *(const float4*)(prev + o);
        float4 mv = *(const float4*)(mask + (size_t)q * W_ + k0 + tn*4);
        float4 r;
        r.x = acc[i][0]*scale + pv.x + mv.x;
        r.y = acc[i][1]*scale + pv.y + mv.y;
        r.z = acc[i][2]*scale + pv.z + mv.z;
        r.w = acc[i][3]*scale + pv.w + mv.w;
        *(float4*)(qk + o) = r;
    }
}

// ---------------------------------------------------------------------------
// Fused softmax + P*V.  One block = (bch, 32 q rows).
// smem: p[32][1024] (exp'd rows), Vs[64][129] chunk, rs[32] (1/rowsum).
// Output a[b,c, f=h*64+d, w=q].
// ---------------------------------------------------------------------------
#define SMAX_SMEM ((32*1024 + 64*129 + 32) * 4)

__global__ void __launch_bounds__(256) softmax_av_kernel(
    const float* __restrict__ qk, const float* __restrict__ V, float* __restrict__ A)
{
    extern __shared__ float sm[];
    float* p  = sm;                   // 32 * 1024
    float* Vs = sm + 32*1024;         // 64 * 129
    float* rs = Vs + 64*129;          // 32

    const int bch = blockIdx.y;
    const int q0  = blockIdx.x * 32;
    const int tid = threadIdx.x, lane = tid & 31, warp = tid >> 5;

    // ---- Phase 1: softmax of 32 rows (each warp owns 4 rows)
    for (int r = warp*4; r < warp*4 + 4; r++) {
        const float* row = qk + ((size_t)bch * W_ + q0 + r) * W_;
        float* pr = p + r * W_;
        float mx = -1e30f;
        #pragma unroll
        for (int i = 0; i < 32; i++) {
            float v = row[lane + i*32];
            pr[lane + i*32] = v;
            mx = fmaxf(mx, v);
        }
        #pragma unroll
        for (int o = 16; o; o >>= 1) mx = fmaxf(mx, __shfl_xor_sync(0xffffffffu, mx, o));
        float s = 0.f;
        #pragma unroll
        for (int i = 0; i < 32; i++) {
            float e = __expf(pr[lane + i*32] - mx);
            pr[lane + i*32] = e;
            s += e;
        }
        #pragma unroll
        for (int o = 16; o; o >>= 1) s += __shfl_xor_sync(0xffffffffu, s, o);
        if (lane == 0) rs[r] = 1.0f / s;
    }
    __syncthreads();

    // ---- Phase 2: a[d][q] = sum_k p[q][k] * V[d][k], V chunked through smem
    const int h  = bch & (H_ - 1);
    const int bc = bch >> 3;
    const size_t fbase = (size_t)bc * F_ + h * DH_;
    const int d0 = (tid & 31) * 2;     // 2 d per thread
    const int qr = (tid >> 5) * 4;     // 4 q per thread

    float acc[2][4] = {};
    for (int kc = 0; kc < W_; kc += 128) {
        #pragma unroll
        for (int t = 0; t < 8; t++) {
            int i  = tid + t * 256;      // over 2048 float4 (64 x 128 floats)
            int d  = i >> 5;
            int kk = (i & 31) * 4;
            float4 v = *(const float4*)(V + (fbase + d) * W_ + kc + kk);
            float* vr = Vs + d*129 + kk;
            vr[0] = v.x; vr[1] = v.y; vr[2] = v.z; vr[3] = v.w;
        }
        __syncthreads();
        #pragma unroll 4
        for (int kk = 0; kk < 128; kk++) {
            float v0 = Vs[(d0  )*129 + kk];
            float v1 = Vs[(d0+1)*129 + kk];
            #pragma unroll
            for (int j = 0; j < 4; j++) {
                float pj = p[(qr+j)*W_ + kc + kk];
                acc[0][j] += v0 * pj;
                acc[1][j] += v1 * pj;
            }
        }
        __syncthreads();
    }

    #pragma unroll
    for (int i = 0; i < 2; i++)
        #pragma unroll
        for (int j = 0; j < 4; j++)
            A[(fbase + d0 + i) * W_ + q0 + qr + j] = acc[i][j] * rs[qr + j];
}

// ---------------------------------------------------------------------------
extern "C" void kernel_launch(void* const* d_in, const int* in_sizes, int n_in,
                              void* d_out, int out_size)
{
    const float* x    = (const float*)d_in[0];
    const float* prev = (const float*)d_in[1];
    const float* mask = (const float*)d_in[2];
    const float* wq   = (const float*)d_in[3];
    const float* wqc  = (const float*)d_in[4];
    const float* bq   = (const float*)d_in[5];
    const float* wk   = (const float*)d_in[6];
    const float* wkc  = (const float*)d_in[7];
    const float* bk   = (const float*)d_in[8];
    const float* wv   = (const float*)d_in[9];
    const float* wvc  = (const float*)d_in[10];
    const float* bv   = (const float*)d_in[11];
    const float* wo   = (const float*)d_in[12];

    float* out = (float*)d_out;            // [B,C,F,W]
    float* qk  = out + (size_t)TOT_;       // [B,C,H,W,W]

    float *lin_base, *conv_base, *abuf;
    cudaGetSymbolAddress((void**)&lin_base,  g_lin);
    cudaGetSymbolAddress((void**)&conv_base, g_conv);
    cudaGetSymbolAddress((void**)&abuf,      g_abuf);
    float* lin0  = lin_base;
    float* lin1  = lin_base + (size_t)TOT_;
    float* lin2  = lin_base + (size_t)2*TOT_;
    float* cbuf0 = conv_base;
    float* cbuf1 = conv_base + (size_t)TOT_;
    float* cbuf2 = conv_base + (size_t)2*TOT_;

    dim3 gg(W_/64, F_/64, BC_);  // 16, 8, 8
    gemm_lin_kernel<<<gg, 256>>>(wq, x, lin0);
    gemm_lin_kernel<<<gg, 256>>>(wk, x, lin1);
    gemm_lin_kernel<<<gg, 256>>>(wv, x, lin2);

    int cblocks = TOT_ / 256;
    conv_kernel<<<cblocks, 256>>>(lin0, wqc, bq, cbuf0);
    conv_kernel<<<cblocks, 256>>>(lin1, wkc, bk, cbuf1);
    conv_kernel<<<cblocks, 256>>>(lin2, wvc, bv, cbuf2);

    int rblocks = (BCH_ * 32 * W_) / 256;
    rotary_kernel<<<rblocks, 256>>>(cbuf0);
    rotary_kernel<<<rblocks, 256>>>(cbuf1);

    qk_kernel<<<dim3(W_/64, W_/64, BCH_), 256>>>(cbuf0, cbuf1, prev, mask, qk);

    cudaFuncSetAttribute(softmax_av_kernel,
                         cudaFuncAttributeMaxDynamicSharedMemorySize, SMAX_SMEM);
    softmax_av_kernel<<<dim3(W_/32, BCH_), 256, SMAX_SMEM>>>(qk, cbuf2, abuf);

    gemm_lin_kernel<<<gg, 256>>>(wo, abuf, out);
}

// round 2
// speedup vs baseline: 1.0006x; 1.0006x over previous
#include <cuda_runtime.h>
#include <math.h>

// Problem constants
#define B_   2
#define C_   4
#define F_   512
#define H_   8
#define W_   1024
#define DH_  64
#define KW   3
#define BC_  (B_*C_)          // 8
#define BCH_ (B_*C_*H_)       // 64
#define PLANE_ (F_*W_)        // 524288 per (b,c)
#define TOT_   (B_*C_*F_*W_)  // 4194304

// Scratch (device globals; no allocations allowed)
__device__ float g_lin[3][TOT_];
__device__ float g_conv[3][TOT_];
__device__ float g_abuf[TOT_];

// ---------------------------------------------------------------------------
// Per-channel GEMM: Y[bc][g][w] = sum_f Wt[c][g][f] * X[bc][f][w]
// Tiles: 64x64 output, K-tile 16, 256 threads, 4x4 register microtile.
// ---------------------------------------------------------------------------
__global__ void __launch_bounds__(256) gemm_lin_kernel(
    const float* __restrict__ Wt, const float* __restrict__ X, float* __restrict__ Y)
{
    const int bc = blockIdx.z;
    const int c  = bc % C_;
    const float* Wc = Wt + (size_t)c * F_ * F_;
    const float* Xb = X  + (size_t)bc * PLANE_;
    float*       Yb = Y  + (size_t)bc * PLANE_;

    __shared__ float As[16][64];   // As[k][m]
    __shared__ float Bs[16][64];   // Bs[k][n]

    const int tid = threadIdx.x;
    const int tn  = tid & 15;      // 0..15
    const int tm  = tid >> 4;      // 0..15
    const int m0  = blockIdx.y * 64;
    const int n0  = blockIdx.x * 64;

    float acc[4][4] = {};

    for (int k0 = 0; k0 < F_; k0 += 16) {
        // A tile: 64 m x 16 k, each thread one float4 along k
        {
            int m  = tid >> 2;           // 0..63
            int kk = (tid & 3) * 4;      // 0,4,8,12
            float4 a = *(const float4*)(Wc + (size_t)(m0 + m) * F_ + k0 + kk);
            As[kk+0][m] = a.x; As[kk+1][m] = a.y; As[kk+2][m] = a.z; As[kk+3][m] = a.w;
        }
        // B tile: 16 k x 64 n, coalesced float4
        {
            int kk = tid >> 4;           // 0..15
            int nn = (tid & 15) * 4;
            *(float4*)&Bs[kk][nn] = *(const float4*)(Xb + (size_t)(k0 + kk) * W_ + n0 + nn);
        }
        __syncthreads();
        #pragma unroll
        for (int kk = 0; kk < 16; kk++) {
            float4 a = *(const float4*)&As[kk][tm*4];
            float4 b = *(const float4*)&Bs[kk][tn*4];
            float ra[4] = {a.x,a.y,a.z,a.w};
            float rb[4] = {b.x,b.y,b.z,b.w};
            #pragma unroll
            for (int i = 0; i < 4; i++)
                #pragma unroll
                for (int j = 0; j < 4; j++)
                    acc[i][j] += ra[i] * rb[j];
        }
        __syncthreads();
    }
    #pragma unroll
    for (int i = 0; i < 4; i++) {
        float4 v = make_float4(acc[i][0], acc[i][1], acc[i][2], acc[i][3]);
        *(float4*)(Yb + (size_t)(m0 + tm*4 + i) * W_ + n0 + tn*4) = v;
    }
}

// ---------------------------------------------------------------------------
// Conv2d(C,C,(1,3),pad=(0,1)) + bias.  y[b,o,f,w] = b[o] + sum_{i,k} w[o,i,k]*x[b,i,f,w+k-1]
// ---------------------------------------------------------------------------
__global__ void __launch_bounds__(256) conv_kernel(
    const float* __restrict__ X, const float* __restrict__ Wc,
    const float* __restrict__ bias, float* __restrict__ Y)
{
    __shared__ float ws[C_*C_*KW];
    __shared__ float bs[C_];
    if (threadIdx.x < C_*C_*KW) ws[threadIdx.x] = Wc[threadIdx.x];
    if (threadIdx.x < C_)       bs[threadIdx.x] = bias[threadIdx.x];
    __syncthreads();

    int idx = blockIdx.x * 256 + threadIdx.x;
    if (idx >= TOT_) return;
    int w = idx & (W_ - 1);
    int f = (idx >> 10) & (F_ - 1);
    int o = (idx >> 19) & (C_ - 1);
    int b = idx >> 21;

    float s = bs[o];
    #pragma unroll
    for (int i = 0; i < C_; i++) {
        const float* xr = X + ((size_t)(b*C_ + i) * F_ + f) * W_ + w;
        #pragma unroll
        for (int k = 0; k < KW; k++) {
            int ww = w + k - 1;
            if (ww >= 0 && ww < W_)
                s += ws[(o*C_ + i)*KW + k] * xr[k - 1];
        }
    }
    Y[idx] = s;
}

// ---------------------------------------------------------------------------
// Interleaved rotary over seq=w, head dim 64 (feature f = h*64 + d), in place.
// ---------------------------------------------------------------------------
__global__ void __launch_bounds__(256) rotary_kernel(float* __restrict__ X)
{
    int pid = blockIdx.x * 256 + threadIdx.x;       // over BCH_*32*W_
    if (pid >= BCH_ * 32 * W_) return;
    int w   = pid & (W_ - 1);
    int j   = (pid >> 10) & 31;                     // pair index 0..31
    int bch = pid >> 15;
    int h   = bch & (H_ - 1);
    int bc  = bch >> 3;

    size_t base = ((size_t)bc * F_ + h * DH_ + 2*j) * W_ + w;
    float x0 = X[base];
    float x1 = X[base + W_];

    float inv = (float)exp(-log(10000.0) * ((double)(2*j) / 64.0));
    float ang = (float)w * inv;
    float sn, cs;
    sincosf(ang, &sn, &cs);

    X[base]       = x0 * cs - x1 * sn;
    X[base + W_]  = x1 * cs + x0 * sn;
}

// ---------------------------------------------------------------------------
// qk[bch][q][k] = (1/sqrt(512)) * sum_d Q[d][q]*K[d][k] + prev + mask
// 64x64 tile per block, K=64 fully in smem.
// ---------------------------------------------------------------------------
__global__ void __launch_bounds__(256) qk_kernel(
    const float* __restrict__ Q, const float* __restrict__ Kb,
    const float* __restrict__ prev, const float* __restrict__ mask,
    float* __restrict__ qk)
{
    const int bch = blockIdx.z;
    const int h   = bch & (H_ - 1);
    const int bc  = bch >> 3;
    const size_t fbase = (size_t)bc * F_ + h * DH_;
    const int q0 = blockIdx.y * 64;
    const int k0 = blockIdx.x * 64;

    __shared__ float Qs[64][64];
    __shared__ float Ks[64][64];

    const int tid = threadIdx.x;
    #pragma unroll
    for (int t = 0; t < 4; t++) {
        int i  = tid + t * 256;       // over 1024 float4 per tile
        int d  = i >> 4;
        int qq = (i & 15) * 4;
        *(float4*)&Qs[d][qq] = *(const float4*)(Q  + (fbase + d) * W_ + q0 + qq);
        *(float4*)&Ks[d][qq] = *(const float4*)(Kb + (fbase + d) * W_ + k0 + qq);
    }
    __syncthreads();

    const int tn = tid & 15, tm = tid >> 4;
    float acc[4][4] = {};
    #pragma unroll
    for (int d = 0; d < 64; d++) {
        float4 a = *(const float4*)&Qs[d][tm*4];
        float4 b = *(const float4*)&Ks[d][tn*4];
        float ra[4] = {a.x,a.y,a.z,a.w};
        float rb[4] = {b.x,b.y,b.z,b.w};
        #pragma unroll
        for (int i = 0; i < 4; i++)
            #pragma unroll
            for (int j = 0; j < 4; j++)
                acc[i][j] += ra[i] * rb[j];
    }

    const float scale = 0.044194173824159216f;   // 1/sqrt(512)
    #pragma unroll
    for (int i = 0; i < 4; i++) {
        int q = q0 + tm*4 + i;
        size_t o = ((size_t)bch * W_ + q) * W_ + k0 + tn*4;
        float4 pv = *(const float4*)(prev + o);
        float4 mv = *(const float4*)(mask + (size_t)q * W_ + k0 + tn*4);
        float4 r;
        r.x = acc[i][0]*scale + pv.x + mv.x;
        r.y = acc[i][1]*scale + pv.y + mv.y;
        r.z = acc[i][2]*scale + pv.z + mv.z;
        r.w = acc[i][3]*scale + pv.w + mv.w;
        *(float4*)(qk + o) = r;
    }
}

// ---------------------------------------------------------------------------
// Fused softmax + P*V.  One block = (bch, 32 q rows).
// smem: p[32][1024] (exp'd rows), Vs[64][129] chunk, rs[32] (1/rowsum).
// Output a[b,c, f=h*64+d, w=q].
// ---------------------------------------------------------------------------
#define SMAX_SMEM ((32*1024 + 64*129 + 32) * 4)

__global__ void __launch_bounds__(256) softmax_av_kernel(
    const float* __restrict__ qk, const float* __restrict__ V, float* __restrict__ A)
{
    extern __shared__ float sm[];
    float* p  = sm;                   // 32 * 1024
    float* Vs = sm + 32*1024;         // 64 * 129
    float* rs = Vs + 64*129;          // 32

    const int bch = blockIdx.y;
    const int q0  = blockIdx.x * 32;
    const int tid = threadIdx.x, lane = tid & 31, warp = tid >> 5;

    // ---- Phase 1: softmax of 32 rows (each warp owns 4 rows)
    for (int r = warp*4; r < warp*4 + 4; r++) {
        const float* row = qk + ((size_t)bch * W_ + q0 + r) * W_;
        float* pr = p + r * W_;
        float mx = -1e30f;
        #pragma unroll
        for (int i = 0; i < 32; i++) {
            float v = row[lane + i*32];
            pr[lane + i*32] = v;
            mx = fmaxf(mx, v);
        }
        #pragma unroll
        for (int o = 16; o; o >>= 1) mx = fmaxf(mx, __shfl_xor_sync(0xffffffffu, mx, o));
        float s = 0.f;
        #pragma unroll
        for (int i = 0; i < 32; i++) {
            float e = __expf(pr[lane + i*32] - mx);
            pr[lane + i*32] = e;
            s += e;
        }
        #pragma unroll
        for (int o = 16; o; o >>= 1) s += __shfl_xor_sync(0xffffffffu, s, o);
        if (lane == 0) rs[r] = 1.0f / s;
    }
    __syncthreads();

    // ---- Phase 2: a[d][q] = sum_k p[q][k] * V[d][k], V chunked through smem
    const int h  = bch & (H_ - 1);
    const int bc = bch >> 3;
    const size_t fbase = (size_t)bc * F_ + h * DH_;
    const int d0 = (tid & 31) * 2;     // 2 d per thread
    const int qr = (tid >> 5) * 4;     // 4 q per thread

    float acc[2][4] = {};
    for (int kc = 0; kc < W_; kc += 128) {
        #pragma unroll
        for (int t = 0; t < 8; t++) {
            int i  = tid + t * 256;      // over 2048 float4 (64 x 128 floats)
            int d  = i >> 5;
            int kk = (i & 31) * 4;
            float4 v = *(const float4*)(V + (fbase + d) * W_ + kc + kk);
            float* vr = Vs + d*129 + kk;
            vr[0] = v.x; vr[1] = v.y; vr[2] = v.z; vr[3] = v.w;
        }
        __syncthreads();
        #pragma unroll 4
        for (int kk = 0; kk < 128; kk++) {
            float v0 = Vs[(d0  )*129 + kk];
            float v1 = Vs[(d0+1)*129 + kk];
            #pragma unroll
            for (int j = 0; j < 4; j++) {
                float pj = p[(qr+j)*W_ + kc + kk];
                acc[0][j] += v0 * pj;
                acc[1][j] += v1 * pj;
            }
        }
        __syncthreads();
    }

    #pragma unroll
    for (int i = 0; i < 2; i++)
        #pragma unroll
        for (int j = 0; j < 4; j++)
            A[(fbase + d0 + i) * W_ + q0 + qr + j] = acc[i][j] * rs[qr + j];
}

// ---------------------------------------------------------------------------
extern "C" void kernel_launch(void* const* d_in, const int* in_sizes, int n_in,
                              void* d_out, int out_size)
{
    const float* x    = (const float*)d_in[0];
    const float* prev = (const float*)d_in[1];
    const float* mask = (const float*)d_in[2];
    const float* wq   = (const float*)d_in[3];
    const float* wqc  = (const float*)d_in[4];
    const float* bq   = (const float*)d_in[5];
    const float* wk   = (const float*)d_in[6];
    const float* wkc  = (const float*)d_in[7];
    const float* bk   = (const float*)d_in[8];
    const float* wv   = (const float*)d_in[9];
    const float* wvc  = (const float*)d_in[10];
    const float* bv   = (const float*)d_in[11];
    const float* wo   = (const float*)d_in[12];

    float* out = (float*)d_out;            // [B,C,F,W]
    float* qk  = out + (size_t)TOT_;       // [B,C,H,W,W]

    float *lin_base, *conv_base, *abuf;
    cudaGetSymbolAddress((void**)&lin_base,  g_lin);
    cudaGetSymbolAddress((void**)&conv_base, g_conv);
    cudaGetSymbolAddress((void**)&abuf,      g_abuf);
    float* lin0  = lin_base;
    float* lin1  = lin_base + (size_t)TOT_;
    float* lin2  = lin_base + (size_t)2*TOT_;
    float* cbuf0 = conv_base;
    float* cbuf1 = conv_base + (size_t)TOT_;
    float* cbuf2 = conv_base + (size_t)2*TOT_;

    dim3 gg(W_/64, F_/64, BC_);  // 16, 8, 8
    gemm_lin_kernel<<<gg, 256>>>(wq, x, lin0);
    gemm_lin_kernel<<<gg, 256>>>(wk, x, lin1);
    gemm_lin_kernel<<<gg, 256>>>(wv, x, lin2);

    int cblocks = TOT_ / 256;
    conv_kernel<<<cblocks, 256>>>(lin0, wqc, bq, cbuf0);
    conv_kernel<<<cblocks, 256>>>(lin1, wkc, bk, cbuf1);
    conv_kernel<<<cblocks, 256>>>(lin2, wvc, bv, cbuf2);

    int rblocks = (BCH_ * 32 * W_) / 256;
    rotary_kernel<<<rblocks, 256>>>(cbuf0);
    rotary_kernel<<<rblocks, 256>>>(cbuf1);

    qk_kernel<<<dim3(W_/64, W_/64, BCH_), 256>>>(cbuf0, cbuf1, prev, mask, qk);

    cudaFuncSetAttribute(softmax_av_kernel,
                         cudaFuncAttributeMaxDynamicSharedMemorySize, SMAX_SMEM);
    softmax_av_kernel<<<dim3(W_/32, BCH_), 256, SMAX_SMEM>>>(qk, cbuf2, abuf);

    gemm_lin_kernel<<<gg, 256>>>(wo, abuf, out);
}